// round 8
// baseline (speedup 1.0000x reference)
#include <cuda_runtime.h>
#include <math.h>

#define DINLINE __device__ __forceinline__

// ---------------- problem constants ----------------
constexpr int kB  = 8;
constexpr int kF  = 257;
constexpr int kL  = 497;
constexpr int kFL = kF * kL;            // 127729
constexpr int kLN = 62;
constexpr int kT  = kL - kLN;           // 435
constexpr int kF2 = 129;
constexpr int kL2 = 249;
constexpr int kFL2 = kF2 * kL2;         // 32121
constexpr int kNBF = kB * kF;           // 2056
constexpr float kBETA = 0.995f;

constexpr long long N_Y    = 16349312;
constexpr long long N_WS2  = 1021832;

// scratch capacities (elements)
constexpr long long RTF_N  = 16349312;
constexpr long long E1_N   = 32698624;
constexpr long long SKIP_N = 32698624;
constexpr long long D1_N   = 16445952;
constexpr long long MID_N  = 16445952;
constexpr long long U2_N   = 32698624;
constexpr long long IS_N   = 131584;    // float2 elements

// d_out layout: float32, complex outputs stored as REAL PART ONLY.
// W_tc[16349312] | re(X_hat)[1021832] | Y[16349312] | re(Wc)[8174656] | W_stage2[1021832] | gate[32698624]
constexpr long long OFF_WTC  = 0;
constexpr long long OFF_XHAT = 16349312;
constexpr long long OFF_Y    = 17371144;
constexpr long long OFF_WC   = 33720456;
constexpr long long OFF_WS2  = 41895112;
constexpr long long OFF_GATE = 42916944;
constexpr long long OUT_TOTAL = 75615568;

struct OutCfg { long long cap; };

__device__ float  g_rtf [RTF_N];
__device__ float  g_e1  [E1_N];
__device__ float  g_skip[SKIP_N];
__device__ float  g_d1  [D1_N];
__device__ float  g_mid [MID_N];
__device__ float  g_u2  [U2_N];
__device__ float2 g_IS  [IS_N];
__device__ float2 g_RS  [IS_N];

// ---- clamped accessors ----
DINLINE float ldc(const float* p, long long i, long long n) {
    if (i < 0) i = 0;
    if (i >= n) i = n - 1;
    return p[i];
}
DINLINE float2 ldc2(const float2* p, long long i, long long n) {
    if (i < 0) i = 0;
    if (i >= n) i = n - 1;
    return p[i];
}
DINLINE void stc(float* p, long long i, long long n, float v) {
    if (i >= 0 && i < n) p[i] = v;
}
DINLINE void stc2(float2* p, long long i, long long n, float2 v) {
    if (i >= 0 && i < n) p[i] = v;
}
DINLINE void sto(float* out, const OutCfg& c, long long idx, float v) {
    if (idx >= 0 && idx < c.cap) out[idx] = v;
}

// =====================================================================
// Kernel 1: Rn + Newton-Schulz -> g_IS (Rn^-1/2), g_RS (Rn^+1/2).
// One warp per (b,f).
// =====================================================================
struct PrepSh {
    float2 stage[8 * 62];
    float2 buf[4][64];
};

DINLINE void mm8(float2* C, const float2* A, const float2* B, int lane) {
    #pragma unroll
    for (int r = 0; r < 2; ++r) {
        int e  = lane + 32 * r;
        int mm = e >> 3, nn = e & 7;
        float2 acc = make_float2(0.f, 0.f);
        #pragma unroll
        for (int k = 0; k < 8; ++k) {
            float2 a  = A[mm * 8 + k];
            float2 bv = B[k * 8 + nn];
            acc.x += a.x * bv.x - a.y * bv.y;
            acc.y += a.x * bv.y + a.y * bv.x;
        }
        C[e] = acc;
    }
}

__global__ __launch_bounds__(256) void k_prep(const float* __restrict__ Y, long long nY) {
    __shared__ PrepSh sh[8];
    const int lane = threadIdx.x & 31;
    const int wrp  = threadIdx.x >> 5;
    const int bf   = blockIdx.x * 8 + wrp;
    if (bf >= kNBF) return;
    PrepSh& S = sh[wrp];
    const int b = bf / kF;
    const int f = bf - b * kF;

    for (int i = lane; i < 8 * 62; i += 32) {
        int m = i / 62, t = i - m * 62;
        long long base = (long long)f * kL + t;
        S.stage[i] = make_float2(ldc(Y, ((long long)(b * 16 + m)) * kFL + base, nY),
                                 ldc(Y, ((long long)(b * 16 + 8 + m)) * kFL + base, nY));
    }
    __syncwarp();

    for (int e = lane; e < 64; e += 32) {
        int mm = e >> 3, nn = e & 7;
        float2 acc = make_float2(0.f, 0.f);
        for (int t = 0; t < 62; ++t) {
            float2 a = S.stage[mm * 62 + t];
            float2 c = S.stage[nn * 62 + t];
            acc.x += a.x * c.x + a.y * c.y;
            acc.y += a.y * c.x - a.x * c.y;
        }
        acc.x *= (1.f / 62.f);
        acc.y *= (1.f / 62.f);
        if (mm == nn) acc.x += 1e-4f;
        S.buf[0][e] = acc;
    }
    __syncwarp();

    float tr = 0.f;
    #pragma unroll
    for (int k = 0; k < 8; ++k) tr += S.buf[0][k * 9].x;
    const float invtr = 1.f / tr;

    for (int e = lane; e < 64; e += 32) {
        float2 v = S.buf[0][e];
        S.buf[0][e] = make_float2(v.x * invtr, v.y * invtr);
        S.buf[1][e] = make_float2(((e >> 3) == (e & 7)) ? 1.f : 0.f, 0.f);
    }
    __syncwarp();

    int iY = 0, iZ = 1, iT = 2, iS = 3;
    for (int it = 0; it < 18; ++it) {
        mm8(S.buf[iT], S.buf[iZ], S.buf[iY], lane);
        __syncwarp();
        for (int e = lane; e < 64; e += 32) {
            float2 pv = S.buf[iT][e];
            S.buf[iT][e] = make_float2((((e >> 3) == (e & 7)) ? 1.5f : 0.f) - 0.5f * pv.x,
                                       -0.5f * pv.y);
        }
        __syncwarp();
        mm8(S.buf[iS], S.buf[iY], S.buf[iT], lane);
        __syncwarp();
        mm8(S.buf[iY], S.buf[iT], S.buf[iZ], lane);
        __syncwarp();
        int tmp = iY; iY = iS; iS = iZ; iZ = tmp;
    }

    const float sq = sqrtf(tr), isq = 1.f / sq;
    for (int e = lane; e < 64; e += 32) {
        float2 y = S.buf[iY][e];
        float2 z = S.buf[iZ][e];
        stc2(g_RS, (long long)bf * 64 + e, IS_N, make_float2(y.x * sq,  y.y * sq));
        stc2(g_IS, (long long)bf * 64 + e, IS_N, make_float2(z.x * isq, z.y * isq));
    }
}

// =====================================================================
// Kernel 2: whitening + PAST-d scan + RTF -> g_rtf
// =====================================================================
DINLINE float2 shfl2(float2 v, int src) {
    float2 r;
    r.x = __shfl_sync(0xffffffffu, v.x, src, 8);
    r.y = __shfl_sync(0xffffffffu, v.y, src, 8);
    return r;
}

__global__ __launch_bounds__(256) void k_scan(const float* __restrict__ Y, long long nY) {
    const int lane = threadIdx.x & 31;
    const int seg  = lane >> 3;
    const int m    = lane & 7;
    const int g    = (blockIdx.x * 8 + (threadIdx.x >> 5)) * 4 + seg;
    const bool valid = (g < kNBF);
    const int gc = valid ? g : 0;
    const int b = gc / kF;
    const int f = gc - b * kF;

    float2 ISr[8], RSr[8];
    #pragma unroll
    for (int n = 0; n < 8; ++n) {
        ISr[n] = ldc2(g_IS, (long long)gc * 64 + m * 8 + n, IS_N);
        RSr[n] = ldc2(g_RS, (long long)gc * 64 + m * 8 + n, IS_N);
    }

    const long long yre0 = ((long long)(b * 16 + m)) * kFL + (long long)f * kL;
    const long long yim0 = yre0 + 8LL * kFL;

    if (valid) {
        for (int t = 0; t < kLN; ++t) {
            stc(g_rtf, yre0 + t, RTF_N, 0.f);
            stc(g_rtf, yim0 + t, RTF_N, 0.f);
        }
    }

    float2 w = make_float2(0.f, 0.f);
    float  d = 1.f;

    for (int t = 0; t < kT; ++t) {
        float2 yc = make_float2(ldc(Y, yre0 + kLN + t, nY), ldc(Y, yim0 + kLN + t, nY));
        float2 y = make_float2(0.f, 0.f);
        #pragma unroll
        for (int n = 0; n < 8; ++n) {
            float2 v = shfl2(yc, n);
            y.x += ISr[n].x * v.x - ISr[n].y * v.y;
            y.y += ISr[n].x * v.y + ISr[n].y * v.x;
        }
        if (t == 0) {
            float nn = y.x * y.x + y.y * y.y;
            #pragma unroll
            for (int o = 4; o; o >>= 1) nn += __shfl_xor_sync(0xffffffffu, nn, o, 8);
            float inv = 1.f / (sqrtf(nn) + 1e-8f);
            w = make_float2(y.x * inv, y.y * inv);
            d = 1.f;
        }
        float2 p = make_float2(y.x * w.x + y.y * w.y, y.y * w.x - y.x * w.y);
        #pragma unroll
        for (int o = 4; o; o >>= 1) {
            p.x += __shfl_xor_sync(0xffffffffu, p.x, o, 8);
            p.y += __shfl_xor_sync(0xffffffffu, p.y, o, 8);
        }
        d = kBETA * d + (p.x * p.x + p.y * p.y);
        float2 e = make_float2(y.x - (w.x * p.x - w.y * p.y),
                               y.y - (w.x * p.y + w.y * p.x));
        float id = 1.f / d;
        float2 cpd = make_float2(p.x * id, -p.y * id);
        w.x += e.x * cpd.x - e.y * cpd.y;
        w.y += e.x * cpd.y + e.y * cpd.x;

        float2 a = make_float2(0.f, 0.f);
        #pragma unroll
        for (int n = 0; n < 8; ++n) {
            float2 v = shfl2(w, n);
            a.x += RSr[n].x * v.x - RSr[n].y * v.y;
            a.y += RSr[n].x * v.y + RSr[n].y * v.x;
        }
        float2 rf = shfl2(a, 3);
        rf.x += 1e-6f;
        float inv2 = 1.f / (rf.x * rf.x + rf.y * rf.y);
        float ox = (a.x * rf.x + a.y * rf.y) * inv2;
        float oy = (a.y * rf.x - a.x * rf.y) * inv2;
        if (valid) {
            stc(g_rtf, yre0 + kLN + t, RTF_N, ox);
            stc(g_rtf, yim0 + kLN + t, RTF_N, oy);
        }
    }
}

// =====================================================================
// Kernel 3: Y echo + W_stage2 zeros
// =====================================================================
__global__ void k_copy(const float* __restrict__ Y, long long nY, float* __restrict__ out, OutCfg c) {
    long long i = (long long)blockIdx.x * blockDim.x + threadIdx.x;
    if (i < N_Y) sto(out, c, OFF_Y + i, ldc(Y, i, nY));
    if (i < N_WS2) sto(out, c, OFF_WS2 + i, 0.0f);
}

// =====================================================================
// Direct conv 3x3 (SAME) — static smem, scalar reads.
// =====================================================================
template<int CIN, int COUT, int STRIDE, int MODE_IN, int MODE_OUT>
__global__ __launch_bounds__(256) void k_conv(
    const float* __restrict__ Yin, long long nY,
    const float* __restrict__ wgt, long long nW,
    const float* __restrict__ bias, long long nBias,
    const float* __restrict__ gw, long long nGw,
    const float* __restrict__ gb, long long nGb,
    float* __restrict__ dout,
    int H_IN, int W_IN, int H_OUT, int W_OUT, int nTiles, OutCfg cfg)
{
    __shared__ float wsh[CIN * 9 * COUT];
    __shared__ float bsh[COUT];
    __shared__ float gsh[(MODE_OUT == 1) ? 1024 : 1];
    __shared__ float gbsh[(MODE_OUT == 1) ? 32 : 1];

    const int b     = blockIdx.z / nTiles;
    const int ct    = blockIdx.z - b * nTiles;
    const int cbase = ct * COUT;

    for (int i = threadIdx.x; i < CIN * 9 * COUT; i += 256) {
        int ci = i / (9 * COUT);
        int r  = i - ci * 9 * COUT;
        int t  = r / COUT;
        int co = r - t * COUT;
        wsh[i] = ldc(wgt, ((long long)(cbase + co) * CIN + ci) * 9 + t, nW);
    }
    for (int i = threadIdx.x; i < COUT; i += 256) bsh[i] = ldc(bias, cbase + i, nBias);
    if (MODE_OUT == 1) {
        for (int i = threadIdx.x; i < 1024; i += 256) {
            int ci = i >> 5, co = i & 31;
            gsh[ci * 32 + co] = ldc(gw, co * 32 + ci, nGw);
        }
        if (threadIdx.x < 32) gbsh[threadIdx.x] = ldc(gb, threadIdx.x, nGb);
    }
    __syncthreads();

    const int l = blockIdx.x * 32 + (threadIdx.x & 31);
    const int f = blockIdx.y * 8 + (threadIdx.x >> 5);
    if (f >= H_OUT || l >= W_OUT) return;

    int off[9];
    if (MODE_IN == 2) {
        int rr[3], cc[3];
        #pragma unroll
        for (int k = 0; k < 3; ++k) {
            int r = f + k - 1;
            rr[k] = (r >= 0 && r < 257) ? ((2 * r + 1) * 129) / 514 : -1;
            int c = l + k - 1;
            cc[k] = (c >= 0 && c < 497) ? ((2 * c + 1) * 249) / 994 : -1;
        }
        #pragma unroll
        for (int t = 0; t < 9; ++t) {
            int kh = t / 3, kw = t - kh * 3;
            off[t] = (rr[kh] >= 0 && cc[kw] >= 0) ? rr[kh] * kL2 + cc[kw] : -1;
        }
    } else {
        #pragma unroll
        for (int t = 0; t < 9; ++t) {
            int r = f * STRIDE + t / 3 - 1;
            int c = l * STRIDE + (t - (t / 3) * 3) - 1;
            off[t] = (r >= 0 && r < H_IN && c >= 0 && c < W_IN) ? r * W_IN + c : -1;
        }
    }

    float acc[COUT];
    #pragma unroll
    for (int co = 0; co < COUT; ++co) acc[co] = bsh[co];

    #pragma unroll 1
    for (int ci = 0; ci < CIN; ++ci) {
        float xv[9];
        #pragma unroll
        for (int t = 0; t < 9; ++t) {
            float v = 0.0f;
            if (off[t] >= 0) {
                if (MODE_IN == 1) {
                    if (ci < 16) v = ldc(Yin, ((long long)(b * 16 + ci)) * kFL + off[t], nY);
                    else         v = ldc(g_rtf, ((long long)(b * 16 + ci - 16)) * kFL + off[t], RTF_N);
                } else if (MODE_IN == 4) {
                    v = ldc(g_e1, ((long long)(b * 32 + ci)) * kFL + off[t], E1_N);
                } else if (MODE_IN == 5) {
                    v = ldc(g_d1, ((long long)(b * 64 + ci)) * kFL2 + off[t], D1_N);
                } else if (MODE_IN == 2) {
                    v = ldc(g_mid, ((long long)(b * 64 + ci)) * kFL2 + off[t], MID_N);
                } else {
                    if (ci < 32) v = ldc(g_u2, ((long long)(b * 32 + ci)) * kFL + off[t], U2_N);
                    else         v = ldc(g_skip, ((long long)(b * 32 + ci - 32)) * kFL + off[t], SKIP_N);
                }
            }
            xv[t] = v;
        }

        #pragma unroll
        for (int t = 0; t < 9; ++t) {
            const float x = xv[t];
            const int wb = ci * 9 * COUT + t * COUT;
            #pragma unroll
            for (int co = 0; co < COUT; ++co)
                acc[co] = fmaf(x, wsh[wb + co], acc[co]);
        }
    }

    const long long pix = (long long)f * W_OUT + l;

    if (MODE_OUT == 1) {
        float e1v[32];
        #pragma unroll
        for (int co = 0; co < 32; ++co) e1v[co] = fmaxf(acc[co], 0.0f);
        #pragma unroll
        for (int co = 0; co < 32; ++co)
            stc(g_e1, ((long long)(b * 32 + co)) * kFL + pix, E1_N, e1v[co]);

        float ga[32];
        #pragma unroll
        for (int co = 0; co < 32; ++co) ga[co] = gbsh[co];
        #pragma unroll 1
        for (int ci = 0; ci < 32; ++ci) {
            float ev = e1v[ci];
            #pragma unroll
            for (int co = 0; co < 32; ++co)
                ga[co] = fmaf(ev, gsh[ci * 32 + co], ga[co]);
        }
        #pragma unroll
        for (int co = 0; co < 32; ++co) {
            float gv = 1.0f / (1.0f + __expf(-ga[co]));
            sto(dout, cfg, OFF_GATE + ((long long)(b * 32 + co)) * kFL + pix, gv);
            stc(g_skip, ((long long)(b * 32 + co)) * kFL + pix, SKIP_N, e1v[co] * gv);
        }
    } else if (MODE_OUT == 2) {
        float wr[8], wi[8];
        #pragma unroll
        for (int co = 0; co < 16; ++co) {
            float s = 1.0f / (1.0f + __expf(-acc[co]));
            sto(dout, cfg, OFF_WTC + ((long long)(b * 16 + co)) * kFL + pix, s);
            if (co < 8) wr[co] = s; else wi[co - 8] = s;
        }
        float xr = 0.f;
        #pragma unroll
        for (int m = 0; m < 8; ++m) {
            float yr = ldc(Yin, ((long long)(b * 16 + m)) * kFL + pix, nY);
            float yi = ldc(Yin, ((long long)(b * 16 + 8 + m)) * kFL + pix, nY);
            xr += wr[m] * yr + wi[m] * yi;                          // real(conj(Wc)*Yc)
            sto(dout, cfg, OFF_WC + ((long long)(b * 8 + m)) * kFL + pix, wr[m]);  // real(Wc)
        }
        sto(dout, cfg, OFF_XHAT + (long long)b * kFL + pix, xr);    // real(X_hat)
    } else {
        #pragma unroll
        for (int co = 0; co < COUT; ++co) {
            float v = fmaxf(acc[co], 0.0f);
            if (MODE_OUT == 10)
                stc(g_d1, ((long long)(b * 64 + cbase + co)) * kFL2 + pix, D1_N, v);
            else if (MODE_OUT == 11)
                stc(g_mid, ((long long)(b * 64 + cbase + co)) * kFL2 + pix, MID_N, v);
            else
                stc(g_u2, ((long long)(b * 32 + cbase + co)) * kFL + pix, U2_N, v);
        }
    }
}

// =====================================================================
extern "C" void kernel_launch(void* const* d_in, const int* in_sizes, int n_in,
                              void* d_out, int out_size)
{
    const float *Y = nullptr, *mid_w = nullptr, *gate_w = nullptr, *out_b16 = nullptr;
    long long szY = 0, szMidW = 0, szGateW = 0, szOutB = 0;
    const float *w9216[2]  = {nullptr, nullptr};  long long s9216[2]  = {0,0};  int n9216  = 0;
    const float *w18432[2] = {nullptr, nullptr};  long long s18432[2] = {0,0};  int n18432 = 0;
    const float *b64[2]    = {nullptr, nullptr};  long long sb64[2]   = {0,0};  int nb64   = 0;
    const float *b32[3]    = {nullptr, nullptr, nullptr}; long long sb32[3] = {0,0,0}; int nb32 = 0;
    for (int i = 0; i < n_in; ++i) {
        const float* p = (const float*)d_in[i];
        long long s = in_sizes[i];
        switch (in_sizes[i]) {
            case 16349312: if (!Y) { Y = p; szY = s; } break;
            case 36864:    mid_w = p; szMidW = s; break;
            case 1024:     gate_w = p; szGateW = s; break;
            case 16:       out_b16 = p; szOutB = s; break;
            case 9216:     if (n9216  < 2) { s9216[n9216] = s;   w9216[n9216++]   = p; } break;
            case 18432:    if (n18432 < 2) { s18432[n18432] = s; w18432[n18432++] = p; } break;
            case 64:       if (nb64   < 2) { sb64[nb64] = s;     b64[nb64++]      = p; } break;
            case 32:       if (nb32   < 3) { sb32[nb32] = s;     b32[nb32++]      = p; } break;
            default: break;
        }
    }
    if (!Y || n9216 < 2 || n18432 < 2 || !mid_w || !gate_w ||
        nb64 < 2 || nb32 < 3 || !out_b16)
        return;

    const float* enc1_w = w9216[0];
    const float* out_w  = w9216[1];
    const float* down_w = w18432[0];
    const float* up_w   = w18432[1];
    const float* down_b = b64[0];
    const float* mid_b  = b64[1];
    const float* enc1_b = b32[0];
    const float* gate_b = b32[1];
    const float* up_b   = b32[2];

    float* out = (float*)d_out;
    const long long os = (long long)out_size;
    OutCfg cfg;
    // Theory (R7 evidence): out_size = 75,615,568 float32 elements; complex stored real-only.
    cfg.cap = (os == OUT_TOTAL) ? OUT_TOTAL : (os / 4);  // fall back to byte-safe cap if theory wrong

    k_prep<<<257, 256>>>(Y, szY);
    k_scan<<<65, 256>>>(Y, szY);
    k_copy<<<63865, 256>>>(Y, szY, out, cfg);

    k_conv<32, 32, 1, 1, 1><<<dim3(16, 33, 8), 256>>>(
        Y, szY, enc1_w, s9216[0], enc1_b, sb32[0], gate_w, szGateW, gate_b, sb32[1],
        out, 257, 497, 257, 497, 1, cfg);
    k_conv<32, 32, 2, 4, 10><<<dim3(8, 17, 16), 256>>>(
        Y, szY, down_w, s18432[0], down_b, sb64[0], nullptr, 0, nullptr, 0,
        out, 257, 497, 129, 249, 2, cfg);
    k_conv<64, 16, 1, 5, 11><<<dim3(8, 17, 32), 256>>>(
        Y, szY, mid_w, szMidW, mid_b, sb64[1], nullptr, 0, nullptr, 0,
        out, 129, 249, 129, 249, 4, cfg);
    k_conv<64, 16, 1, 2, 12><<<dim3(16, 33, 16), 256>>>(
        Y, szY, up_w, s18432[1], up_b, sb32[2], nullptr, 0, nullptr, 0,
        out, 257, 497, 257, 497, 2, cfg);
    k_conv<64, 16, 1, 3, 2><<<dim3(16, 33, 8), 256>>>(
        Y, szY, out_w, s9216[1], out_b16, szOutB, nullptr, 0, nullptr, 0,
        out, 257, 497, 257, 497, 1, cfg);
}